// round 1
// baseline (speedup 1.0000x reference)
#include <cuda_runtime.h>
#include <cfloat>
#include <stdint.h>

#define N_NODES 100000
#define N_EDGES 1600000
#define BGRAPH  64
#define DINP    9
#define H       128
#define EPS     1e-5f

#define SCAN_BLK 512
#define SCAN_NB  196   // ceil(100000/512)

// ---------------- scratch (device globals; no allocation allowed) -----------
__device__ float g_hA[N_NODES * H];
__device__ float g_hB[N_NODES * H];
__device__ float g_agg[N_NODES * H];
__device__ float g_Wt[3 * 256 * H];     // per-layer [256][128] = [Wl;Wr] transposed
__device__ int   g_rowptr[N_NODES + 1];
__device__ int   g_col[N_EDGES];
__device__ int   g_deg[N_NODES];
__device__ int   g_cursor[N_NODES];
__device__ int   g_bsum[SCAN_NB];
__device__ int   g_start[BGRAPH + 1];

// ---------------- f32x2 helpers (Blackwell packed fp32) ---------------------
__device__ __forceinline__ unsigned long long pack2(float v) {
    unsigned long long r;
    unsigned u = __float_as_uint(v);
    asm("mov.b64 %0, {%1, %2};" : "=l"(r) : "r"(u), "r"(u));
    return r;
}
#define FMA2(d, a, b) asm("fma.rn.f32x2 %0, %1, %2, %0;" : "+l"(d) : "l"(a), "l"(b))

__device__ __forceinline__ float f2lo(unsigned long long v) {
    return __uint_as_float((unsigned)(v & 0xffffffffull));
}
__device__ __forceinline__ float f2hi(unsigned long long v) {
    return __uint_as_float((unsigned)(v >> 32));
}

// ---------------- CSR build -------------------------------------------------
__global__ void k_zero() {
    int i = blockIdx.x * blockDim.x + threadIdx.x;
    if (i < N_NODES) { g_deg[i] = 0; g_cursor[i] = 0; }
}

__global__ void k_deg(const int* __restrict__ dst) {
    int e = blockIdx.x * blockDim.x + threadIdx.x;
    if (e < N_EDGES) atomicAdd(&g_deg[dst[e]], 1);
}

__global__ void k_scan1() {
    __shared__ int sh[SCAN_BLK];
    int t = threadIdx.x;
    int i = blockIdx.x * SCAN_BLK + t;
    int v = (i < N_NODES) ? g_deg[i] : 0;
    sh[t] = v; __syncthreads();
    for (int o = 1; o < SCAN_BLK; o <<= 1) {
        int a = (t >= o) ? sh[t - o] : 0;
        __syncthreads();
        sh[t] += a;
        __syncthreads();
    }
    if (i < N_NODES) g_rowptr[i] = sh[t] - v;   // local exclusive
    if (t == SCAN_BLK - 1) g_bsum[blockIdx.x] = sh[t];
}

__global__ void k_scan2() {
    __shared__ int sh[256];
    int t = threadIdx.x;
    int v = (t < SCAN_NB) ? g_bsum[t] : 0;
    sh[t] = v; __syncthreads();
    for (int o = 1; o < 256; o <<= 1) {
        int a = (t >= o) ? sh[t - o] : 0;
        __syncthreads();
        sh[t] += a;
        __syncthreads();
    }
    if (t < SCAN_NB) g_bsum[t] = sh[t] - v;     // exclusive block offsets
    if (t == 0) g_rowptr[N_NODES] = N_EDGES;
}

__global__ void k_scan3() {
    int i = blockIdx.x * SCAN_BLK + threadIdx.x;
    if (i < N_NODES) g_rowptr[i] += g_bsum[blockIdx.x];
}

__global__ void k_scatter(const int* __restrict__ src, const int* __restrict__ dst) {
    int e = blockIdx.x * blockDim.x + threadIdx.x;
    if (e < N_EDGES) {
        int d = dst[e];
        int p = atomicAdd(&g_cursor[d], 1);
        g_col[g_rowptr[d] + p] = src[e];
    }
}

// ---------------- weight pre-transpose: Wt[k][c] = k<H ? Wl[c][k] : Wr[c][k-H]
__global__ void k_wt(const float* __restrict__ Wl1, const float* __restrict__ Wr1,
                     const float* __restrict__ Wl2, const float* __restrict__ Wr2,
                     const float* __restrict__ Wl3, const float* __restrict__ Wr3) {
    int idx = blockIdx.x * blockDim.x + threadIdx.x;
    if (idx >= 3 * 256 * H) return;
    int l = idx / (256 * H);
    int r = idx % (256 * H);
    int k = r / H, c = r % H;
    const float* Wl = (l == 0) ? Wl1 : (l == 1) ? Wl2 : Wl3;
    const float* Wr = (l == 0) ? Wr1 : (l == 1) ? Wr2 : Wr3;
    g_Wt[idx] = (k < H) ? Wl[c * H + k] : Wr[c * H + (k - H)];
}

// ---------------- node embedder: relu(LN(x @ W0^T + b0)) --------------------
__global__ void k_embed(const float* __restrict__ x, const float* __restrict__ W0,
                        const float* __restrict__ b0, const float* __restrict__ g0,
                        const float* __restrict__ be0) {
    int gw = (blockIdx.x * blockDim.x + threadIdx.x) >> 5;
    int lane = threadIdx.x & 31;
    if (gw >= N_NODES) return;
    float xd = (lane < DINP) ? x[gw * DINP + lane] : 0.f;
    float xs[DINP];
#pragma unroll
    for (int d = 0; d < DINP; d++) xs[d] = __shfl_sync(0xffffffffu, xd, d);
    float o[4];
#pragma unroll
    for (int j = 0; j < 4; j++) {
        int c = lane * 4 + j;
        float acc = b0[c];
#pragma unroll
        for (int d = 0; d < DINP; d++) acc = fmaf(xs[d], W0[c * DINP + d], acc);
        o[j] = acc;
    }
    float s1 = o[0] + o[1] + o[2] + o[3];
    float s2 = o[0]*o[0] + o[1]*o[1] + o[2]*o[2] + o[3]*o[3];
#pragma unroll
    for (int off = 16; off; off >>= 1) {
        s1 += __shfl_xor_sync(0xffffffffu, s1, off);
        s2 += __shfl_xor_sync(0xffffffffu, s2, off);
    }
    float m  = s1 * (1.f / H);
    float var = fmaxf(s2 * (1.f / H) - m * m, 0.f);
    float rs = rsqrtf(var + EPS);
    float4 out;
    float* po = &out.x;
#pragma unroll
    for (int j = 0; j < 4; j++) {
        int c = lane * 4 + j;
        po[j] = fmaxf((o[j] - m) * rs * g0[c] + be0[c], 0.f);
    }
    *(float4*)&g_hA[(size_t)gw * H + lane * 4] = out;
}

// ---------------- mean aggregation over CSR: warp per destination node ------
__global__ void k_agg(const float* __restrict__ h) {
    int gw = (blockIdx.x * blockDim.x + threadIdx.x) >> 5;
    int lane = threadIdx.x & 31;
    if (gw >= N_NODES) return;
    int s = g_rowptr[gw], e = g_rowptr[gw + 1];
    float4 acc = make_float4(0.f, 0.f, 0.f, 0.f);
    for (int p = s; p < e; p++) {
        int sn = __ldg(&g_col[p]);
        float4 v = *(const float4*)(h + (size_t)sn * H + lane * 4);
        acc.x += v.x; acc.y += v.y; acc.z += v.z; acc.w += v.w;
    }
    float inv = 1.f / fmaxf((float)(e - s), 1.f);
    acc.x *= inv; acc.y *= inv; acc.z *= inv; acc.w *= inv;
    *(float4*)(g_agg + (size_t)gw * H + lane * 4) = acc;
}

// ---------------- fused dual-GEMM + LayerNorm + ReLU ------------------------
// out[n] = relu(LN( [agg_n ; h_n] (1x256) @ Wt (256x128) + bl ))
// Tile: 64 nodes x 128 channels per block, K streamed in chunks of 32.
__global__ void __launch_bounds__(256, 2) k_layer(
    const float* __restrict__ h, const float* __restrict__ Wt,
    const float* __restrict__ bl, const float* __restrict__ gg,
    const float* __restrict__ be, float* __restrict__ out)
{
    __shared__ __align__(16) float As[32][66];    // [k][node]
    __shared__ __align__(16) float Ws[32][132];   // [k][chan]
    int t  = threadIdx.x;
    int tx = t & 31;      // channel group lane
    int ty = t >> 5;      // node-octet (== warp id)
    int nodeBase = blockIdx.x * 64;

    unsigned long long acc[4][4];   // [node-pair][channel] packed f32x2
#pragma unroll
    for (int p = 0; p < 4; p++)
#pragma unroll
        for (int j = 0; j < 4; j++) acc[p][j] = 0ull;

    const int lk = t & 31;   // k within tile for A-loads
    const int ln = t >> 5;   // node sub-index for A-loads

    for (int kk = 0; kk < 256; kk += 32) {
        const float* Asrc = (kk < H) ? g_agg : h;
        int ccol = kk + lk - ((kk < H) ? 0 : H);
#pragma unroll
        for (int it = 0; it < 8; it++) {
            int node = it * 8 + ln;
            int ng = nodeBase + node;
            As[lk][node] = (ng < N_NODES) ? Asrc[(size_t)ng * H + ccol] : 0.f;
        }
#pragma unroll
        for (int it = 0; it < 16; it++) {
            int id = it * 256 + t;
            int k = id >> 7, c = id & 127;
            Ws[k][c] = Wt[(kk + k) * H + c];
        }
        __syncthreads();
#pragma unroll
        for (int k = 0; k < 32; k++) {
            float4 w = *(const float4*)&Ws[k][tx * 4];
            unsigned long long w0 = pack2(w.x), w1 = pack2(w.y),
                               w2 = pack2(w.z), w3 = pack2(w.w);
#pragma unroll
            for (int p = 0; p < 4; p++) {
                unsigned long long a2 = *(const unsigned long long*)&As[k][ty * 8 + p * 2];
                FMA2(acc[p][0], a2, w0);
                FMA2(acc[p][1], a2, w1);
                FMA2(acc[p][2], a2, w2);
                FMA2(acc[p][3], a2, w3);
            }
        }
        __syncthreads();
    }

    float4 blv = *(const float4*)&bl[tx * 4];
    float4 gv  = *(const float4*)&gg[tx * 4];
    float4 bev = *(const float4*)&be[tx * 4];

#pragma unroll
    for (int p = 0; p < 4; p++) {
#pragma unroll
        for (int half = 0; half < 2; half++) {
            float v0 = (half ? f2hi(acc[p][0]) : f2lo(acc[p][0])) + blv.x;
            float v1 = (half ? f2hi(acc[p][1]) : f2lo(acc[p][1])) + blv.y;
            float v2 = (half ? f2hi(acc[p][2]) : f2lo(acc[p][2])) + blv.z;
            float v3 = (half ? f2hi(acc[p][3]) : f2lo(acc[p][3])) + blv.w;
            float s1 = v0 + v1 + v2 + v3;
            float s2 = v0*v0 + v1*v1 + v2*v2 + v3*v3;
#pragma unroll
            for (int off = 16; off; off >>= 1) {
                s1 += __shfl_xor_sync(0xffffffffu, s1, off);
                s2 += __shfl_xor_sync(0xffffffffu, s2, off);
            }
            float m   = s1 * (1.f / H);
            float var = fmaxf(s2 * (1.f / H) - m * m, 0.f);
            float rs  = rsqrtf(var + EPS);
            int ng = nodeBase + ty * 8 + p * 2 + half;
            if (ng < N_NODES) {
                float4 o;
                o.x = fmaxf((v0 - m) * rs * gv.x + bev.x, 0.f);
                o.y = fmaxf((v1 - m) * rs * gv.y + bev.y, 0.f);
                o.z = fmaxf((v2 - m) * rs * gv.z + bev.z, 0.f);
                o.w = fmaxf((v3 - m) * rs * gv.w + bev.w, 0.f);
                *(float4*)&out[(size_t)ng * H + tx * 4] = o;
            }
        }
    }
}

// ---------------- pooling ---------------------------------------------------
__global__ void k_startk(const int* __restrict__ batch) {
    int i = blockIdx.x * blockDim.x + threadIdx.x;
    if (i >= N_NODES) return;
    int b  = batch[i];
    int bp = (i == 0) ? -1 : batch[i - 1];
    for (int g = bp + 1; g <= b; g++) g_start[g] = i;
    if (i == N_NODES - 1)
        for (int g = b + 1; g <= BGRAPH; g++) g_start[g] = N_NODES;
}

__global__ void k_pool(float* __restrict__ out) {
    int b = blockIdx.x;          // graph
    int c = threadIdx.x;         // channel (128 threads)
    int s = g_start[b], e = g_start[b + 1];
    float sum = 0.f, mx = -FLT_MAX;
    const float* ne = out;       // node_embed occupies out[0 .. N*H)
    for (int n = s; n < e; n++) {
        float v = ne[(size_t)n * H + c];
        sum += v;
        mx = fmaxf(mx, v);
    }
    float cnt = (float)(e - s);
    size_t gbase = (size_t)N_NODES * H + (size_t)b * 2 * H;
    out[gbase + c]     = sum / fmaxf(cnt, 1.f);
    out[gbase + H + c] = mx;
}

// ---------------- launch ----------------------------------------------------
extern "C" void kernel_launch(void* const* d_in, const int* in_sizes, int n_in,
                              void* d_out, int out_size) {
    const float* x     = (const float*)d_in[0];
    const int*   ei    = (const int*)  d_in[1];
    const int*   batch = (const int*)  d_in[2];
    const float* W0  = (const float*)d_in[3];
    const float* b0  = (const float*)d_in[4];
    const float* g0  = (const float*)d_in[5];
    const float* be0 = (const float*)d_in[6];
    const float* Wl1 = (const float*)d_in[7];
    const float* bl1 = (const float*)d_in[8];
    const float* Wr1 = (const float*)d_in[9];
    const float* g1  = (const float*)d_in[10];
    const float* be1 = (const float*)d_in[11];
    const float* Wl2 = (const float*)d_in[12];
    const float* bl2 = (const float*)d_in[13];
    const float* Wr2 = (const float*)d_in[14];
    const float* g2  = (const float*)d_in[15];
    const float* be2 = (const float*)d_in[16];
    const float* Wl3 = (const float*)d_in[17];
    const float* bl3 = (const float*)d_in[18];
    const float* Wr3 = (const float*)d_in[19];
    const float* g3  = (const float*)d_in[20];
    const float* be3 = (const float*)d_in[21];

    const int* src = ei;
    const int* dst = ei + N_EDGES;
    float* out = (float*)d_out;

    float *hA, *hB, *Wt;
    cudaGetSymbolAddress((void**)&hA, g_hA);
    cudaGetSymbolAddress((void**)&hB, g_hB);
    cudaGetSymbolAddress((void**)&Wt, g_Wt);

    const int nodeBlocks = (N_NODES + 255) / 256;
    const int edgeBlocks = (N_EDGES + 255) / 256;
    const int warpBlocks = (N_NODES + 7) / 8;          // 8 warps/block
    const int tileBlocks = (N_NODES + 63) / 64;

    // CSR build (every launch — caching is forbidden)
    k_zero<<<nodeBlocks, 256>>>();
    k_deg<<<edgeBlocks, 256>>>(dst);
    k_scan1<<<SCAN_NB, SCAN_BLK>>>();
    k_scan2<<<1, 256>>>();
    k_scan3<<<SCAN_NB, SCAN_BLK>>>();
    k_scatter<<<edgeBlocks, 256>>>(src, dst);

    k_wt<<<(3 * 256 * H + 255) / 256, 256>>>(Wl1, Wr1, Wl2, Wr2, Wl3, Wr3);

    k_embed<<<warpBlocks, 256>>>(x, W0, b0, g0, be0);

    // layer 1: hA -> hB
    k_agg<<<warpBlocks, 256>>>(hA);
    k_layer<<<tileBlocks, 256>>>(hA, Wt + 0 * 256 * H, bl1, g1, be1, hB);
    // layer 2: hB -> hA
    k_agg<<<warpBlocks, 256>>>(hB);
    k_layer<<<tileBlocks, 256>>>(hB, Wt + 1 * 256 * H, bl2, g2, be2, hA);
    // layer 3: hA -> out (node_embed region)
    k_agg<<<warpBlocks, 256>>>(hA);
    k_layer<<<tileBlocks, 256>>>(hA, Wt + 2 * 256 * H, bl3, g3, be3, out);

    k_startk<<<nodeBlocks, 256>>>(batch);
    k_pool<<<BGRAPH, H>>>(out);
}